// round 15
// baseline (speedup 1.0000x reference)
#include <cuda_runtime.h>
#include <cuda_bf16.h>

// out = K * conv3x3(inp, k), K = linear LIF gain (R1 analysis: I < 9 < 14, so
// the 1000-step LIF never clamps and is exactly linear; K computed host-side
// in double).
//
// R12 (resubmitted R14; two consecutive broker-level container failures gave
// no kernel signal): R6 smem-staging base (best ncu: 23.5us) + store-issue
// fixes. LSU issue accounting (SASS_QUICKREF: STG.64=7.75cyc, STG.128=12cyc)
// shows stores dominate the invariant ~51% "L1" utilization. Changes vs R6:
//  - ROWS=10 (510 = 51*10): halo 1.2x, and the 5100-float linear output tile
//    is float4-aligned in gmem (260100n + 5100by, both %4==0) -> copy-out is
//    LDS.128 + STG.128, conflict-free and fully coalesced.
//  - smem tile stored EXACTLY linear (ROWS*510, no padding); compute stages
//    results with two STS.64 (8B-aligned).
//  - float2 halo loads (24B/row/thread) instead of R6's second float4.

#define H_IN 512
#define W_IN 512
#define H_OUT 510
#define W_OUT 510
#define BATCH 64
#define ROWS 10         // output rows per block (510 = 51 * 10, exact)
#define TPB 128         // each thread covers 4 cols -> 512 >= 510
#define TILE_F4 (ROWS * W_OUT / 4)   // 1275 float4 per block

__global__ __launch_bounds__(TPB) void snn_conv_kernel(
    const float* __restrict__ inp,
    const float* __restrict__ kw,
    float* __restrict__ out,
    float K) {
    __shared__ __align__(16) float stile[ROWS * W_OUT];   // 20400 B, linear

    const int tx = threadIdx.x;
    const int x  = tx * 4;
    const int y0 = blockIdx.y * ROWS;
    const int n  = blockIdx.z;
    const bool full = (tx != TPB - 1);   // tx==127: cols 508-509 only

    // weights with K folded in
    const float k00 = K * kw[0], k01 = K * kw[1], k02 = K * kw[2];
    const float k10 = K * kw[3], k11 = K * kw[4], k12 = K * kw[5];
    const float k20 = K * kw[6], k21 = K * kw[7], k22 = K * kw[8];

    const float* base = inp + ((size_t)n * H_IN + y0) * W_IN + x;

    // rolling 3-row window: float4 (cols x..x+3) + float2 (cols x+4..x+5)
    float4 a[3];
    float2 b[3];

    #pragma unroll
    for (int j = 0; j < 2; j++) {
        const float* p = base + j * W_IN;
        a[j] = *(const float4*)p;
        b[j] = full ? *(const float2*)(p + 4) : make_float2(0.f, 0.f);
    }

    #pragma unroll
    for (int r = 0; r < ROWS; r++) {
        // load input row y0 + r + 2 into slot (r+2)%3
        {
            const float* p = base + (r + 2) * W_IN;
            int s = (r + 2) % 3;
            a[s] = *(const float4*)p;
            b[s] = full ? *(const float2*)(p + 4) : make_float2(0.f, 0.f);
        }

        float o0 = 0.f, o1 = 0.f, o2 = 0.f, o3 = 0.f;

        #pragma unroll
        for (int j = 0; j < 3; j++) {
            int s = (r + j) % 3;
            float w0 = (j == 0) ? k00 : (j == 1) ? k10 : k20;
            float w1 = (j == 0) ? k01 : (j == 1) ? k11 : k21;
            float w2 = (j == 0) ? k02 : (j == 1) ? k12 : k22;
            float4 A = a[s];
            float2 B = b[s];
            o0 = fmaf(w0, A.x, o0); o0 = fmaf(w1, A.y, o0); o0 = fmaf(w2, A.z, o0);
            o1 = fmaf(w0, A.y, o1); o1 = fmaf(w1, A.z, o1); o1 = fmaf(w2, A.w, o1);
            o2 = fmaf(w0, A.z, o2); o2 = fmaf(w1, A.w, o2); o2 = fmaf(w2, B.x, o2);
            o3 = fmaf(w0, A.w, o3); o3 = fmaf(w1, B.x, o3); o3 = fmaf(w2, B.y, o3);
        }

        // stage into the EXACT-linear tile: two 8B-aligned STS.64
        int sb = r * W_OUT + x;
        *(float2*)&stile[sb] = make_float2(o0, o1);
        if (full) *(float2*)&stile[sb + 2] = make_float2(o2, o3);
    }

    __syncthreads();

    // Linear copy-out: rows y0..y0+9 of batch n are 5100 consecutive floats.
    // Base = 260100*n + 5100*blockIdx.y  -> divisible by 4, so float4 all the
    // way: conflict-free LDS.128 + coalesced STG.128.
    float4* o4 = (float4*)(out + ((size_t)n * H_OUT + y0) * W_OUT);
    const float4* s4 = (const float4*)stile;

    #pragma unroll
    for (int it = 0; it < (TILE_F4 + TPB - 1) / TPB; it++) {
        int i = it * TPB + tx;
        if (i < TILE_F4) o4[i] = s4[i];
    }
}

extern "C" void kernel_launch(void* const* d_in, const int* in_sizes, int n_in,
                              void* d_out, int out_size) {
    const float* inp = (const float*)d_in[0];
    const float* kw  = (const float*)d_in[1];
    float* out = (float*)d_out;

    // Host-side linear LIF gain (double precision), I = 1:
    //   v' = v + (-v + R*I) / (R*C) * DT ; vt averaged per reference
    const double R = 3000.0;
    const double C = 10.0;
    const double DT = (double)0.01f;   // reference uses float32 DT
    const double NSTEPS = 1000.0;

    double v = 0.0;
    v = v + (-v + R * 1.0) / (R * C) * DT;   // v0
    double vt = v;
    for (int i = 0; i < 999; i++) {
        v = v + (-v + R * 1.0) / (R * C) * DT;
        vt = (v + vt) / NSTEPS;
    }
    float K = (float)vt;

    dim3 block(TPB, 1, 1);
    dim3 grid(1, H_OUT / ROWS, BATCH);   // 1 x 51 x 64 = 3264 blocks
    snn_conv_kernel<<<grid, block>>>(inp, kw, out, K);
}